// round 7
// baseline (speedup 1.0000x reference)
#include <cuda_runtime.h>
#include <cuda_bf16.h>

#define BDIM 512
#define S_LEN 4096
#define B_ROWS 4096

__device__ float        g_accum = 0.0f;
__device__ unsigned int g_count = 0;

__device__ __forceinline__ float ex2_approx(float x) {
    float r; asm("ex2.approx.f32 %0, %1;" : "=f"(r) : "f"(x)); return r;
}
__device__ __forceinline__ float lg2_approx(float x) {
    float r; asm("lg2.approx.f32 %0, %1;" : "=f"(r) : "f"(x)); return r;
}
__device__ __forceinline__ unsigned opaque_zero(unsigned v) {
    unsigned z;
    asm volatile("and.b32 %0, %1, 0;" : "=r"(z) : "r"(v));
    return z;
}

__global__ __launch_bounds__(BDIM) void mtcut_row_kernel(
    const float* __restrict__ cut_y,
    const int*   __restrict__ cut_label,
    const float* __restrict__ rerank_y,
    float* __restrict__ out)
{
    const int b    = blockIdx.x;
    const int t    = threadIdx.x;
    const int lane = t & 31;
    const int wid  = t >> 5;

    const int4*   l4 = reinterpret_cast<const int4*>(cut_label + (size_t)b * S_LEN);
    const float4* y4 = reinterpret_cast<const float4*>(cut_y + (size_t)b * S_LEN);

    // labels FIRST: the scan barrier depends only on these 32 bytes
    int4   la = __ldcs(&l4[2 * t]);
    int4   lb = __ldcs(&l4[2 * t + 1]);
    // y loads fly in the background; consumed only at the very end
    float4 ya = __ldcs(&y4[2 * t]);
    float4 yb = __ldcs(&y4[2 * t + 1]);

    float labf[8] = {(float)la.x, (float)la.y, (float)la.z, (float)la.w,
                     (float)lb.x, (float)lb.y, (float)lb.z, (float)lb.w};

    // per-thread label sum + warp inclusive scan (float; exact, values <= 4096)
    float tsum = 0.f;
    #pragma unroll
    for (int j = 0; j < 8; j++) tsum += labf[j];

    float incl = tsum;
    #pragma unroll
    for (int d = 1; d < 32; d <<= 1) {
        float v = __shfl_up_sync(0xffffffffu, incl, d);
        if (lane >= d) incl += v;
    }

    __shared__ float wsum[16];
    if (lane == 31) wsum[wid] = incl;
    __syncthreads();                      // the ONLY pre-exp barrier

    // redundant level-2 scan in EVERY warp (16-wide, shuffle)
    float v16 = (lane < 16) ? wsum[lane] : 0.f;
    float s = v16;
    #pragma unroll
    for (int d = 1; d < 16; d <<= 1) {
        float u = __shfl_up_sync(0xffffffffu, s, d);
        if (lane >= d) s += u;
    }
    const float T = __shfl_sync(0xffffffffu, s, 15);          // row total
    float off = __shfl_sync(0xffffffffu, s, (wid == 0) ? 0 : (wid - 1));
    if (wid == 0) off = 0.f;                                   // warp offset

    // exp(r/tau) = ex2( (c*Cx)/(k+T) ),  Cx = 2/(tau*ln2); r=2c/(k+T) is f1
    const float Cx = 2.0f / (0.95f * 0.69314718055994531f);
    float cfx = (off + (incl - tsum)) * Cx;   // exclusive prefix * Cx
    float esum = 0.f;
    float den = (float)(t * 8) + T + 1.0f;
    #pragma unroll
    for (int j = 0; j < 8; j++) {
        cfx = fmaf(labf[j], Cx, cfx);
        esum += ex2_approx(__fdividef(cfx, den));
        den += 1.0f;
    }

    // NOW consume y: sum(log y) = log(prod y), one LG2 per thread.
    // y in (1e-4, 1): prod >= 1e-32 > FLT_MIN, no underflow.
    float p01 = ya.x * ya.y, p23 = ya.z * ya.w;
    float p45 = yb.x * yb.y, p67 = yb.z * yb.w;
    float lg2sum = lg2_approx((p01 * p23) * (p45 * p67));

    // block reduce esum, lg2sum
    #pragma unroll
    for (int d = 16; d; d >>= 1) {
        esum   += __shfl_down_sync(0xffffffffu, esum, d);
        lg2sum += __shfl_down_sync(0xffffffffu, lg2sum, d);
    }
    __shared__ float se[16], sl[16];
    if (lane == 0) { se[wid] = esum; sl[wid] = lg2sum; }
    __syncthreads();

    if (t == 0) {
        float e = 0.f, l = 0.f;
        #pragma unroll
        for (int w = 0; w < 16; w++) { e += se[w]; l += sl[w]; }
        float lsum = l * 0.69314718055994531f;           // lg2 -> ln
        float2 pn = reinterpret_cast<const float2*>(rerank_y)[b];
        float hinge = fmaxf(0.f, pn.y - pn.x + 1.0f);
        float contrib = (hinge - lsum / e) * (1.0f / (float)B_ROWS);

        // L2 atomic accumulate (no fence, no L1 flush)
        float oldv = atomicAdd(&g_accum, contrib);
        unsigned z0 = opaque_zero(__float_as_uint(oldv));
        unsigned rank = atomicAdd(&g_count, 1u + z0);

        if (rank == B_ROWS - 1) {
            unsigned z1 = opaque_zero(rank);
            float total = atomicAdd(&g_accum, __uint_as_float(z1));  // += +0.0f
            out[0] = total;
            unsigned z2 = opaque_zero(__float_as_uint(total));
            atomicExch(&g_accum, __uint_as_float(z2));               // = 0.0f
            atomicExch(&g_count, z2);                                // = 0
        }
    }
}

extern "C" void kernel_launch(void* const* d_in, const int* in_sizes, int n_in,
                              void* d_out, int out_size)
{
    const float* rerank_y  = (const float*)d_in[0];   // (8192,1)
    const float* cut_y     = (const float*)d_in[1];   // (4096,4096,1)
    const int*   cut_label = (const int*)d_in[3];     // (4096,4096)
    float* out = (float*)d_out;

    mtcut_row_kernel<<<B_ROWS, BDIM>>>(cut_y, cut_label, rerank_y, out);
}